// round 5
// baseline (speedup 1.0000x reference)
#include <cuda_runtime.h>

// out[b] = x[b,:]·(sum_o W[o,:]) + sum(b)
// Phase 1: column-reduce W (64 MB) -> partials (4 MB), full-occupancy single wave
// Phase 2: reduce partials -> w_sum[2048]; bias sum
// Phase 3: one dot per batch row (128 MB), exactly one resident wave

#define IN_F   2048
#define OUT_F  8192
#define BATCH  16384
#define VEC4   (IN_F / 4)                      // 512 float4 per row
#define RGROUPS 512
#define ROWS_PER_RG (OUT_F / RGROUPS)          // 16

__device__ float g_partial[RGROUPS * IN_F];    // 4 MB scratch (deterministic 2-pass)
__device__ float g_wsum[IN_F];
__device__ float g_bsum;

// ---- Pass 1: grid (2,512)=1024 blocks x 256 thr = 262144 threads (~55 warps/SM).
// Each thread: one col4, 16 rows as 4 batches of 4 explicit in-flight loads.
__global__ __launch_bounds__(256, 8) void wsum_partial_kernel(const float* __restrict__ W) {
    int col4 = blockIdx.x * 256 + threadIdx.x;           // 0..511
    int rg   = blockIdx.y;                               // 0..511
    const float4* W4 = reinterpret_cast<const float4*>(W)
                       + (size_t)rg * ROWS_PER_RG * VEC4 + col4;
    float4 acc = make_float4(0.f, 0.f, 0.f, 0.f);
    #pragma unroll
    for (int bt = 0; bt < 4; bt++) {
        float4 v[4];
        #pragma unroll
        for (int i = 0; i < 4; i++)
            v[i] = W4[(size_t)(bt * 4 + i) * VEC4];      // 4 loads in flight
        #pragma unroll
        for (int i = 0; i < 4; i++) {
            acc.x += v[i].x; acc.y += v[i].y; acc.z += v[i].z; acc.w += v[i].w;
        }
    }
    reinterpret_cast<float4*>(g_partial)[rg * VEC4 + col4] = acc;
}

// ---- Pass 2: blocks 0..15 reduce 32 col4 each (8 threads/col4, 64 chunks per thread);
//      block 16 sums bias.  Reads the 4 MB partial array.
__global__ __launch_bounds__(256) void wsum_final_kernel(const float* __restrict__ b) {
    if (blockIdx.x == 16) {
        __shared__ float sh[256];
        float s = 0.f;
        for (int i = threadIdx.x; i < OUT_F; i += 256) s += b[i];
        sh[threadIdx.x] = s;
        __syncthreads();
        #pragma unroll
        for (int o = 128; o > 0; o >>= 1) {
            if (threadIdx.x < o) sh[threadIdx.x] += sh[threadIdx.x + o];
            __syncthreads();
        }
        if (threadIdx.x == 0) g_bsum = sh[0];
        return;
    }
    int lcol = threadIdx.x & 31;                         // 0..31
    int sub  = threadIdx.x >> 5;                         // 0..7 -> 64 rowgroups each
    int col4 = blockIdx.x * 32 + lcol;                   // 0..511
    const float4* P4 = reinterpret_cast<const float4*>(g_partial)
                       + (size_t)(sub * 64) * VEC4 + col4;
    float4 acc = make_float4(0.f, 0.f, 0.f, 0.f);
    #pragma unroll
    for (int bt = 0; bt < 8; bt++) {
        float4 v[8];
        #pragma unroll
        for (int i = 0; i < 8; i++)
            v[i] = P4[(size_t)(bt * 8 + i) * VEC4];
        #pragma unroll
        for (int i = 0; i < 8; i++) {
            acc.x += v[i].x; acc.y += v[i].y; acc.z += v[i].z; acc.w += v[i].w;
        }
    }
    __shared__ float4 sh4[8][32];
    sh4[sub][lcol] = acc;
    __syncthreads();
    if (sub == 0) {
        #pragma unroll
        for (int s = 1; s < 8; s++) {
            float4 a = sh4[s][lcol];
            acc.x += a.x; acc.y += a.y; acc.z += a.z; acc.w += a.w;
        }
        reinterpret_cast<float4*>(g_wsum)[col4] = acc;
    }
}

// ---- Pass 3: 1024 blocks x 256 thr (one full resident wave); each warp does
//      2 rows sequentially (16 rows per block).
__global__ __launch_bounds__(256, 8) void dot_kernel(const float* __restrict__ x,
                                                     float* __restrict__ out) {
    __shared__ float4 sw[VEC4];                          // 8 KB
    int tid = threadIdx.x;
    const float4* Wsum4 = reinterpret_cast<const float4*>(g_wsum);
    sw[tid]       = Wsum4[tid];
    sw[tid + 256] = Wsum4[tid + 256];
    __syncthreads();

    int warp = tid >> 5;
    int lane = tid & 31;
    int base = blockIdx.x * 16;

    float res[2];
    #pragma unroll
    for (int rr = 0; rr < 2; rr++) {
        int row = base + rr * 8 + warp;
        const float4* x4 = reinterpret_cast<const float4*>(x)
                           + (size_t)row * VEC4 + lane;
        float acc = 0.f;
        #pragma unroll
        for (int bt = 0; bt < 4; bt++) {
            float4 v[4];
            #pragma unroll
            for (int i = 0; i < 4; i++)
                v[i] = x4[(bt * 4 + i) * 32];            // 4 loads in flight
            #pragma unroll
            for (int i = 0; i < 4; i++) {
                float4 w = sw[(bt * 4 + i) * 32 + lane];
                acc += v[i].x * w.x + v[i].y * w.y + v[i].z * w.z + v[i].w * w.w;
            }
        }
        #pragma unroll
        for (int o = 16; o > 0; o >>= 1)
            acc += __shfl_xor_sync(0xffffffffu, acc, o);
        res[rr] = acc;
    }

    if (lane == 0) {
        float bs = g_bsum;
        out[base + warp]     = res[0] + bs;
        out[base + 8 + warp] = res[1] + bs;
    }
}

extern "C" void kernel_launch(void* const* d_in, const int* in_sizes, int n_in,
                              void* d_out, int out_size) {
    const float* x = (const float*)d_in[0];   // [16384, 2048]
    const float* W = (const float*)d_in[1];   // [8192, 2048]
    const float* b = (const float*)d_in[2];   // [8192]
    float* out = (float*)d_out;               // [16384, 1]
    (void)in_sizes; (void)n_in; (void)out_size;

    wsum_partial_kernel<<<dim3(2, RGROUPS), 256>>>(W);
    wsum_final_kernel<<<17, 256>>>(b);
    dot_kernel<<<BATCH / 16, 256>>>(x, out);
}

// round 6
// speedup vs baseline: 1.0287x; 1.0287x over previous
#include <cuda_runtime.h>

// out[b] = x[b,:]·(sum_o W[o,:]) + sum(b)
// Phase 1: column-reduce W (64 MB) -> partials (4 MB), full-occupancy single wave
// Phase 2: reduce partials -> w_sum[2048]; bias sum
// Phase 3: one dot per batch row (128 MB), exactly one resident wave

#define IN_F   2048
#define OUT_F  8192
#define BATCH  16384
#define VEC4   (IN_F / 4)                      // 512 float4 per row
#define RGROUPS 512
#define ROWS_PER_RG (OUT_F / RGROUPS)          // 16

__device__ float g_partial[RGROUPS * IN_F];    // 4 MB scratch (deterministic 2-pass)
__device__ float g_wsum[IN_F];
__device__ float g_bsum;

// ---- Pass 1: grid (2,512)=1024 blocks x 256 thr = 262144 threads (~55 warps/SM).
// Each thread: one col4, 16 rows as 4 batches of 4 explicit in-flight loads.
__global__ __launch_bounds__(256, 8) void wsum_partial_kernel(const float* __restrict__ W) {
    int col4 = blockIdx.x * 256 + threadIdx.x;           // 0..511
    int rg   = blockIdx.y;                               // 0..511
    const float4* W4 = reinterpret_cast<const float4*>(W)
                       + (size_t)rg * ROWS_PER_RG * VEC4 + col4;
    float4 acc = make_float4(0.f, 0.f, 0.f, 0.f);
    #pragma unroll
    for (int bt = 0; bt < 4; bt++) {
        float4 v[4];
        #pragma unroll
        for (int i = 0; i < 4; i++)
            v[i] = W4[(size_t)(bt * 4 + i) * VEC4];      // 4 loads in flight
        #pragma unroll
        for (int i = 0; i < 4; i++) {
            acc.x += v[i].x; acc.y += v[i].y; acc.z += v[i].z; acc.w += v[i].w;
        }
    }
    reinterpret_cast<float4*>(g_partial)[rg * VEC4 + col4] = acc;
}

// ---- Pass 2: blocks 0..15 reduce 32 col4 each (8 threads/col4, 64 chunks per thread);
//      block 16 sums bias.  Reads the 4 MB partial array.
__global__ __launch_bounds__(256) void wsum_final_kernel(const float* __restrict__ b) {
    if (blockIdx.x == 16) {
        __shared__ float sh[256];
        float s = 0.f;
        for (int i = threadIdx.x; i < OUT_F; i += 256) s += b[i];
        sh[threadIdx.x] = s;
        __syncthreads();
        #pragma unroll
        for (int o = 128; o > 0; o >>= 1) {
            if (threadIdx.x < o) sh[threadIdx.x] += sh[threadIdx.x + o];
            __syncthreads();
        }
        if (threadIdx.x == 0) g_bsum = sh[0];
        return;
    }
    int lcol = threadIdx.x & 31;                         // 0..31
    int sub  = threadIdx.x >> 5;                         // 0..7 -> 64 rowgroups each
    int col4 = blockIdx.x * 32 + lcol;                   // 0..511
    const float4* P4 = reinterpret_cast<const float4*>(g_partial)
                       + (size_t)(sub * 64) * VEC4 + col4;
    float4 acc = make_float4(0.f, 0.f, 0.f, 0.f);
    #pragma unroll
    for (int bt = 0; bt < 8; bt++) {
        float4 v[8];
        #pragma unroll
        for (int i = 0; i < 8; i++)
            v[i] = P4[(size_t)(bt * 8 + i) * VEC4];
        #pragma unroll
        for (int i = 0; i < 8; i++) {
            acc.x += v[i].x; acc.y += v[i].y; acc.z += v[i].z; acc.w += v[i].w;
        }
    }
    __shared__ float4 sh4[8][32];
    sh4[sub][lcol] = acc;
    __syncthreads();
    if (sub == 0) {
        #pragma unroll
        for (int s = 1; s < 8; s++) {
            float4 a = sh4[s][lcol];
            acc.x += a.x; acc.y += a.y; acc.z += a.z; acc.w += a.w;
        }
        reinterpret_cast<float4*>(g_wsum)[col4] = acc;
    }
}

// ---- Pass 3: 1024 blocks x 256 thr (one full resident wave); each warp does
//      2 rows sequentially (16 rows per block).
__global__ __launch_bounds__(256, 8) void dot_kernel(const float* __restrict__ x,
                                                     float* __restrict__ out) {
    __shared__ float4 sw[VEC4];                          // 8 KB
    int tid = threadIdx.x;
    const float4* Wsum4 = reinterpret_cast<const float4*>(g_wsum);
    sw[tid]       = Wsum4[tid];
    sw[tid + 256] = Wsum4[tid + 256];
    __syncthreads();

    int warp = tid >> 5;
    int lane = tid & 31;
    int base = blockIdx.x * 16;

    float res[2];
    #pragma unroll
    for (int rr = 0; rr < 2; rr++) {
        int row = base + rr * 8 + warp;
        const float4* x4 = reinterpret_cast<const float4*>(x)
                           + (size_t)row * VEC4 + lane;
        float acc = 0.f;
        #pragma unroll
        for (int bt = 0; bt < 4; bt++) {
            float4 v[4];
            #pragma unroll
            for (int i = 0; i < 4; i++)
                v[i] = x4[(bt * 4 + i) * 32];            // 4 loads in flight
            #pragma unroll
            for (int i = 0; i < 4; i++) {
                float4 w = sw[(bt * 4 + i) * 32 + lane];
                acc += v[i].x * w.x + v[i].y * w.y + v[i].z * w.z + v[i].w * w.w;
            }
        }
        #pragma unroll
        for (int o = 16; o > 0; o >>= 1)
            acc += __shfl_xor_sync(0xffffffffu, acc, o);
        res[rr] = acc;
    }

    if (lane == 0) {
        float bs = g_bsum;
        out[base + warp]     = res[0] + bs;
        out[base + 8 + warp] = res[1] + bs;
    }
}

extern "C" void kernel_launch(void* const* d_in, const int* in_sizes, int n_in,
                              void* d_out, int out_size) {
    const float* x = (const float*)d_in[0];   // [16384, 2048]
    const float* W = (const float*)d_in[1];   // [8192, 2048]
    const float* b = (const float*)d_in[2];   // [8192]
    float* out = (float*)d_out;               // [16384, 1]
    (void)in_sizes; (void)n_in; (void)out_size;

    wsum_partial_kernel<<<dim3(2, RGROUPS), 256>>>(W);
    wsum_final_kernel<<<17, 256>>>(b);
    dot_kernel<<<BATCH / 16, 256>>>(x, out);
}